// round 13
// baseline (speedup 1.0000x reference)
#include <cuda_runtime.h>
#include <math.h>
#include <stdint.h>

// ---------------------------------------------------------------------------
// QuickPatternMatchingLoss
//   out[b] = log( (1/ls) * sum_{l: mask} sum_o ss_hmm[o,l] *
//                 softmax_o( W[:, :20] . x[b,1:,l] + slog[:,l] ) )
//   slog[o,l] = b[o] + sum_h W[o,20+h] * seq_hmm[h,l]
//   mask[b,l] = ( max_{c>=1} x[b,c,l] > x[b,0,l] )
//
// R13: R12's decoupled producer/consumer pipe (best main kernel, ~33.8us)
// with the finalize kernel FUSED as a dedicated finalizer warp:
//   warps 0-7: consumers (float2/thread), warp 8: TMA producer,
//   warp 9: finalizer (4-deep smem partial ring, done/free mbarriers).
// Zero __syncthreads in the row loop; single launch. 5.2 TB/s is the
// accepted pattern ceiling (7 structures all plateau there) - the win here
// is removing the 4.8us finalize launch.
// ---------------------------------------------------------------------------

#define MAX_L 2048
__device__ float g_slog[3 * MAX_L];            // fallback path scratch

#define FL 512
#define FC 21
#define FL2 (FL / 2)                            // 256 float2 per channel row
#define ROW_BYTES (FC * FL * 4)                 // 43008
#define GRIDP 304                               // 2 CTAs/SM
#define SMEM_DYN (2 * ROW_BYTES)                // 86016
#define NWC 8                                   // consumer warps
#define NTC (NWC * 32)                          // 256 consumer threads
#define NT (NTC + 64)                           // + producer + finalizer warps
#define NSLOT 4                                 // partial-ring depth

__device__ __forceinline__ uint32_t smem_u32(const void* p) {
    uint32_t a;
    asm("{ .reg .u64 t; cvta.to.shared.u64 t, %1; cvt.u32.u64 %0, t; }"
        : "=r"(a) : "l"(p));
    return a;
}
__device__ __forceinline__ void mbar_init(uint32_t mbar, uint32_t count) {
    asm volatile("mbarrier.init.shared.b64 [%0], %1;" :: "r"(mbar), "r"(count) : "memory");
}
__device__ __forceinline__ void mbar_arrive(uint32_t mbar) {
    asm volatile("mbarrier.arrive.shared.b64 _, [%0];" :: "r"(mbar) : "memory");
}
__device__ __forceinline__ void mbar_expect_tx(uint32_t mbar, uint32_t bytes) {
    asm volatile("mbarrier.arrive.expect_tx.shared.b64 _, [%0], %1;"
                 :: "r"(mbar), "r"(bytes) : "memory");
}
__device__ __forceinline__ void bulk_g2s(uint32_t dst, const void* src,
                                         uint32_t bytes, uint32_t mbar) {
    asm volatile(
        "cp.async.bulk.shared::cta.global.mbarrier::complete_tx::bytes "
        "[%0], [%1], %2, [%3];"
        :: "r"(dst), "l"(src), "r"(bytes), "r"(mbar) : "memory");
}
__device__ __forceinline__ void mbar_wait(uint32_t mbar, uint32_t parity) {
    uint32_t done;
    asm volatile(
        "{\n\t.reg .pred p;\n\t"
        "mbarrier.try_wait.parity.acquire.cta.shared::cta.b64 p, [%1], %2;\n\t"
        "selp.b32 %0, 1, 0, p;\n\t}"
        : "=r"(done) : "r"(mbar), "r"(parity) : "memory");
    if (!done) {
        asm volatile(
            "{\n\t.reg .pred P1;\n\t"
            "WAIT_LOOP_%=:\n\t"
            "mbarrier.try_wait.parity.acquire.cta.shared::cta.b64 P1, [%0], %1, 0x989680;\n\t"
            "@P1 bra.uni WAIT_DONE_%=;\n\t"
            "bra.uni WAIT_LOOP_%=;\n\t"
            "WAIT_DONE_%=:\n\t}"
            :: "r"(mbar), "r"(parity) : "memory");
    }
}

// ---- single-launch pipeline: producer + consumers + finalizer ---------------
__global__ void __launch_bounds__(NT, 2)
qpml_pipe(const float* __restrict__ x,
          const float* __restrict__ seq_hmm,
          const float* __restrict__ ss_hmm,
          const float* __restrict__ W,
          const float* __restrict__ bvec,
          float* __restrict__ out,
          int B, int H, int wstride)
{
    extern __shared__ __align__(16) float dyn[];
    const float2* buf2[2] = { (const float2*)dyn,
                              (const float2*)(dyn + FC * FL) };

    __shared__ float sW0[64], sW1[64], sW2[64];
    __shared__ __align__(8) unsigned long long mb_full[2], mb_empty[2];
    __shared__ __align__(8) unsigned long long mb_done[NSLOT], mb_free[NSLOT];
    __shared__ float2 part[NSLOT][NWC];

    const int t = threadIdx.x;
    const int warp = t >> 5, lane = t & 31;
    const int cta = blockIdx.x;
    const int G = gridDim.x;

    if (t == 0) {
        mbar_init(smem_u32(&mb_full[0]), 1);
        mbar_init(smem_u32(&mb_full[1]), 1);
        mbar_init(smem_u32(&mb_empty[0]), NWC);
        mbar_init(smem_u32(&mb_empty[1]), NWC);
        #pragma unroll
        for (int s = 0; s < NSLOT; ++s) {
            mbar_init(smem_u32(&mb_done[s]), NWC);
            mbar_init(smem_u32(&mb_free[s]), 1);
        }
        // pre-arm free ring: first NSLOT uses pass immediately
        #pragma unroll
        for (int s = 0; s < NSLOT; ++s) mbar_arrive(smem_u32(&mb_free[s]));
    }
    if (t < wstride && t < 64) {
        sW0[t] = __ldg(&W[0 * wstride + t]);
        sW1[t] = __ldg(&W[1 * wstride + t]);
        sW2[t] = __ldg(&W[2 * wstride + t]);
    }
    __syncthreads();   // the ONLY block-wide barrier

    const uint32_t bsm[2] = { smem_u32(buf2[0]), smem_u32(buf2[1]) };
    const uint32_t mf[2]  = { smem_u32(&mb_full[0]), smem_u32(&mb_full[1]) };
    const uint32_t me[2]  = { smem_u32(&mb_empty[0]), smem_u32(&mb_empty[1]) };
    uint32_t mdone[NSLOT], mfree[NSLOT];
    #pragma unroll
    for (int s = 0; s < NSLOT; ++s) {
        mdone[s] = smem_u32(&mb_done[s]);
        mfree[s] = smem_u32(&mb_free[s]);
    }

    if (warp == NWC) {
        // ---------------- producer warp ----------------
        if (lane == 0) {
            int phe[2] = {0, 0};
            int it = 0;
            for (long long r = cta; r < B; r += G, ++it) {
                const int k = it & 1;
                mbar_wait(me[k], phe[k]);      // pre-armed for it=0,1
                phe[k] ^= 1;
                mbar_expect_tx(mf[k], ROW_BYTES);
                bulk_g2s(bsm[k], (const char*)x + (size_t)r * ROW_BYTES,
                         ROW_BYTES, mf[k]);
            }
        }
        return;
    }

    if (warp == NWC + 1) {
        // ---------------- finalizer warp ----------------
        if (lane == 0) {
            int phd[NSLOT] = {0, 0, 0, 0};
            int it = 0;
            for (long long r = cta; r < B; r += G, ++it) {
                const int s = it & (NSLOT - 1);
                mbar_wait(mdone[s], phd[s]);
                phd[s] ^= 1;
                float ssum = 0.f, csum = 0.f;
                #pragma unroll
                for (int w = 0; w < NWC; ++w) {
                    float2 v = part[s][w];
                    ssum += v.x;
                    csum += v.y;
                }
                out[r] = logf(ssum / csum);
                mbar_arrive(mfree[s]);
            }
        }
        return;
    }

    // ---------------- consumer warps ----------------
    // pre-arm both empty barriers (completes phase 0 of each)
    if (lane == 0) { mbar_arrive(me[0]); mbar_arrive(me[1]); }

    // per-thread tables for columns 2t, 2t+1 (overlaps first fills)
    float2 d10, d20, h0c, h1c, h2c;
    {
        float bb0 = __ldg(&bvec[0]), bb1 = __ldg(&bvec[1]), bb2 = __ldg(&bvec[2]);
        float2 s0 = make_float2(bb0, bb0);
        float2 s1 = make_float2(bb1, bb1);
        float2 s2 = make_float2(bb2, bb2);
        for (int h = 0; h < H; ++h) {
            float2 v = __ldg((const float2*)seq_hmm + h * FL2 + t);
            float w0 = sW0[20 + h], w1 = sW1[20 + h], w2 = sW2[20 + h];
            s0.x = fmaf(w0, v.x, s0.x); s0.y = fmaf(w0, v.y, s0.y);
            s1.x = fmaf(w1, v.x, s1.x); s1.y = fmaf(w1, v.y, s1.y);
            s2.x = fmaf(w2, v.x, s2.x); s2.y = fmaf(w2, v.y, s2.y);
        }
        d10 = make_float2(s1.x - s0.x, s1.y - s0.y);
        d20 = make_float2(s2.x - s0.x, s2.y - s0.y);
        h0c = __ldg((const float2*)ss_hmm + 0 * FL2 + t);
        h1c = __ldg((const float2*)ss_hmm + 1 * FL2 + t);
        h2c = __ldg((const float2*)ss_hmm + 2 * FL2 + t);
    }

    int phf[2] = {0, 0};
    int phfree[NSLOT] = {0, 0, 0, 0};
    int it = 0;
    for (long long r = cta; r < B; r += G, ++it) {
        const int k = it & 1;
        const int s = it & (NSLOT - 1);
        const float2* bk = buf2[k];

        mbar_wait(mf[k], phf[k]);
        phf[k] ^= 1;

        // ---- accumulation: ALL smem reads of buf[k] ----
        float2 v0 = bk[t];
        float mxx = -INFINITY, mxy = -INFINITY;
        float a0x = 0.f, a0y = 0.f;
        float a1x = 0.f, a1y = 0.f;
        float a2x = 0.f, a2y = 0.f;
        #pragma unroll
        for (int c = 1; c < FC; ++c) {
            float2 v = bk[c * FL2 + t];
            float w0 = sW0[c - 1], w1 = sW1[c - 1], w2 = sW2[c - 1];
            mxx = fmaxf(mxx, v.x);       mxy = fmaxf(mxy, v.y);
            a0x = fmaf(w0, v.x, a0x);    a0y = fmaf(w0, v.y, a0y);
            a1x = fmaf(w1, v.x, a1x);    a1y = fmaf(w1, v.y, a1y);
            a2x = fmaf(w2, v.x, a2x);    a2y = fmaf(w2, v.y, a2y);
        }

        // release buffer k immediately -- refill overlaps the tail below
        __syncwarp();
        if (lane == 0) mbar_arrive(me[k]);

        // ---- tail (no buf[k] reads): rebased softmax, e0 == 1 ----
        float e1x = __expf((a1x - a0x) + d10.x);
        float e2x = __expf((a2x - a0x) + d20.x);
        float e1y = __expf((a1y - a0y) + d10.y);
        float e2y = __expf((a2y - a0y) + d20.y);
        float numx = fmaf(h2c.x, e2x, fmaf(h1c.x, e1x, h0c.x));
        float denx = 1.f + e1x + e2x;
        float numy = fmaf(h2c.y, e2y, fmaf(h1c.y, e1y, h0c.y));
        float deny = 1.f + e1y + e2y;
        bool mxm = mxx > v0.x;
        bool mym = mxy > v0.y;
        float contrib = (mxm ? __fdividef(numx, denx) : 0.f)
                      + (mym ? __fdividef(numy, deny) : 0.f);
        float cnt = (mxm ? 1.f : 0.f) + (mym ? 1.f : 0.f);

        #pragma unroll
        for (int off = 16; off > 0; off >>= 1) {
            contrib += __shfl_down_sync(0xffffffffu, contrib, off);
            cnt     += __shfl_down_sync(0xffffffffu, cnt, off);
        }
        if (lane == 0) {
            // backpressure vs finalizer (4-row slack; fast-path in practice)
            mbar_wait(mfree[s], phfree[s]);
            phfree[s] ^= 1;
            part[s][warp] = make_float2(contrib, cnt);
            mbar_arrive(mdone[s]);
        }
    }
}

// ---- fallback paths (non-512x21 shapes) --------------------------------------
__global__ void slog_kernel(const float* __restrict__ seq_hmm,
                            const float* __restrict__ W,
                            const float* __restrict__ bvec,
                            int L, int H, int wstride)
{
    int l = blockIdx.x * blockDim.x + threadIdx.x;
    if (l >= L) return;
    float s0 = bvec[0], s1 = bvec[1], s2 = bvec[2];
    for (int h = 0; h < H; ++h) {
        float v = __ldg(&seq_hmm[h * L + l]);
        s0 = fmaf(__ldg(&W[0 * wstride + 20 + h]), v, s0);
        s1 = fmaf(__ldg(&W[1 * wstride + 20 + h]), v, s1);
        s2 = fmaf(__ldg(&W[2 * wstride + 20 + h]), v, s2);
    }
    g_slog[0 * L + l] = s0;
    g_slog[1 * L + l] = s1;
    g_slog[2 * L + l] = s2;
}

__global__ void __launch_bounds__(128, 6)
qpml_generic(const float* __restrict__ x,
             const float* __restrict__ ss_hmm,
             const float* __restrict__ W,
             float* __restrict__ out,
             int L, int C, int wstride)
{
    const int b = blockIdx.x;
    const int t = threadIdx.x;
    const int Lv = L >> 2;

    __shared__ float sW0[20], sW1[20], sW2[20];
    if (t < 20) {
        sW0[t] = __ldg(&W[0 * wstride + t]);
        sW1[t] = __ldg(&W[1 * wstride + t]);
        sW2[t] = __ldg(&W[2 * wstride + t]);
    }
    __syncthreads();

    const float4* xb = (const float4*)(x + (size_t)b * (size_t)C * (size_t)L);
    float contrib = 0.f, cnt = 0.f;

    for (int i = t; i < Lv; i += 128) {
        float4 sl0 = __ldg((const float4*)&g_slog[0 * L] + i);
        float4 sl1 = __ldg((const float4*)&g_slog[1 * L] + i);
        float4 sl2 = __ldg((const float4*)&g_slog[2 * L] + i);
        float4 h0  = __ldg((const float4*)&ss_hmm[0 * L] + i);
        float4 h1  = __ldg((const float4*)&ss_hmm[1 * L] + i);
        float4 h2  = __ldg((const float4*)&ss_hmm[2 * L] + i);

        float4 v0 = __ldcs(&xb[i]);
        float x0[4] = {v0.x, v0.y, v0.z, v0.w};
        float mx[4] = {-INFINITY, -INFINITY, -INFINITY, -INFINITY};
        float a0[4] = {0.f, 0.f, 0.f, 0.f};
        float a1[4] = {0.f, 0.f, 0.f, 0.f};
        float a2[4] = {0.f, 0.f, 0.f, 0.f};

        for (int c = 1; c < C; ++c) {
            float4 v = __ldcs(&xb[c * Lv + i]);
            float vv[4] = {v.x, v.y, v.z, v.w};
            float w0 = sW0[c - 1], w1 = sW1[c - 1], w2 = sW2[c - 1];
            #pragma unroll
            for (int j = 0; j < 4; ++j) {
                mx[j] = fmaxf(mx[j], vv[j]);
                a0[j] = fmaf(w0, vv[j], a0[j]);
                a1[j] = fmaf(w1, vv[j], a1[j]);
                a2[j] = fmaf(w2, vv[j], a2[j]);
            }
        }

        float sla0[4] = {sl0.x, sl0.y, sl0.z, sl0.w};
        float sla1[4] = {sl1.x, sl1.y, sl1.z, sl1.w};
        float sla2[4] = {sl2.x, sl2.y, sl2.z, sl2.w};
        float ha0[4]  = {h0.x, h0.y, h0.z, h0.w};
        float ha1[4]  = {h1.x, h1.y, h1.z, h1.w};
        float ha2[4]  = {h2.x, h2.y, h2.z, h2.w};

        #pragma unroll
        for (int j = 0; j < 4; ++j) {
            float e0 = __expf(a0[j] + sla0[j]);
            float e1 = __expf(a1[j] + sla1[j]);
            float e2 = __expf(a2[j] + sla2[j]);
            float num = ha0[j] * e0 + ha1[j] * e1 + ha2[j] * e2;
            float den = e0 + e1 + e2;
            bool m = mx[j] > x0[j];
            contrib += m ? __fdividef(num, den) : 0.f;
            cnt     += m ? 1.f : 0.f;
        }
    }

    #pragma unroll
    for (int off = 16; off > 0; off >>= 1) {
        contrib += __shfl_down_sync(0xffffffffu, contrib, off);
        cnt     += __shfl_down_sync(0xffffffffu, cnt, off);
    }
    __shared__ float rs[2][4];
    if ((t & 31) == 0) { rs[0][t >> 5] = contrib; rs[1][t >> 5] = cnt; }
    __syncthreads();
    if (t == 0) {
        float s = rs[0][0] + rs[0][1] + rs[0][2] + rs[0][3];
        float c = rs[1][0] + rs[1][1] + rs[1][2] + rs[1][3];
        out[b] = logf(s / c);
    }
}

__global__ void qpml_kernel_scalar(const float* __restrict__ x,
                                   const float* __restrict__ ss_hmm,
                                   const float* __restrict__ W,
                                   float* __restrict__ out,
                                   int L, int C, int wstride)
{
    const int b = blockIdx.x;
    const int t = threadIdx.x;
    const float* xb = x + (size_t)b * (size_t)C * (size_t)L;

    float contrib = 0.f, cnt = 0.f;
    for (int l = t; l < L; l += blockDim.x) {
        float x0 = xb[l];
        float mx = -INFINITY;
        float a0 = 0.f, a1 = 0.f, a2 = 0.f;
        for (int c = 1; c < C; ++c) {
            float v = xb[c * L + l];
            mx = fmaxf(mx, v);
            a0 = fmaf(W[0 * wstride + c - 1], v, a0);
            a1 = fmaf(W[1 * wstride + c - 1], v, a1);
            a2 = fmaf(W[2 * wstride + c - 1], v, a2);
        }
        float e0 = __expf(a0 + g_slog[0 * L + l]);
        float e1 = __expf(a1 + g_slog[1 * L + l]);
        float e2 = __expf(a2 + g_slog[2 * L + l]);
        float num = ss_hmm[0 * L + l] * e0 + ss_hmm[1 * L + l] * e1
                  + ss_hmm[2 * L + l] * e2;
        if (mx > x0) { contrib += num / (e0 + e1 + e2); cnt += 1.f; }
    }
    #pragma unroll
    for (int off = 16; off > 0; off >>= 1) {
        contrib += __shfl_down_sync(0xffffffffu, contrib, off);
        cnt     += __shfl_down_sync(0xffffffffu, cnt, off);
    }
    __shared__ float rs[2][32];
    int nw = (blockDim.x + 31) >> 5;
    if ((t & 31) == 0) { rs[0][t >> 5] = contrib; rs[1][t >> 5] = cnt; }
    __syncthreads();
    if (t == 0) {
        float s = 0.f, c = 0.f;
        for (int w = 0; w < nw; ++w) { s += rs[0][w]; c += rs[1][w]; }
        out[b] = logf(s / c);
    }
}

extern "C" void kernel_launch(void* const* d_in, const int* in_sizes, int n_in,
                              void* d_out, int out_size)
{
    const float* x       = (const float*)d_in[0];   // [B, 21, L]
    const float* seq_hmm = (const float*)d_in[1];   // [H, L]
    const float* ss_hmm  = (const float*)d_in[2];   // [3, L]
    const float* W       = (const float*)d_in[3];   // [3, 20+H]
    const float* bvec    = (const float*)d_in[4];   // [3]
    float* out = (float*)d_out;

    const int B       = out_size;                   // 4096
    const int L       = in_sizes[2] / 3;            // 512
    const int H       = in_sizes[1] / L;            // 30
    const int C       = in_sizes[0] / (B * L);      // 21
    const int wstride = in_sizes[3] / 3;            // 20 + H = 50

    if (C == FC && L == FL && H <= 44 && wstride <= 64) {
        cudaFuncSetAttribute(qpml_pipe,
                             cudaFuncAttributeMaxDynamicSharedMemorySize,
                             SMEM_DYN);
        int grid = (B < GRIDP) ? B : GRIDP;
        qpml_pipe<<<grid, NT, SMEM_DYN>>>(x, seq_hmm, ss_hmm, W, bvec, out,
                                          B, H, wstride);
    } else if ((L & 3) == 0 && L <= MAX_L) {
        slog_kernel<<<(L + 255) / 256, 256>>>(seq_hmm, W, bvec, L, H, wstride);
        qpml_generic<<<B, 128>>>(x, ss_hmm, W, out, L, C, wstride);
    } else {
        slog_kernel<<<(L + 255) / 256, 256>>>(seq_hmm, W, bvec, L, H, wstride);
        qpml_kernel_scalar<<<B, 128>>>(x, ss_hmm, W, out, L, C, wstride);
    }
}

// round 14
// speedup vs baseline: 1.1457x; 1.1457x over previous
#include <cuda_runtime.h>
#include <math.h>
#include <stdint.h>

// ---------------------------------------------------------------------------
// QuickPatternMatchingLoss
//   out[b] = log( (1/ls) * sum_{l: mask} sum_o ss_hmm[o,l] *
//                 softmax_o( W[:, :20] . x[b,1:,l] + slog[:,l] ) )
//   slog[o,l] = b[o] + sum_h W[o,20+h] * seq_hmm[h,l]
//   mask[b,l] = ( max_{c>=1} x[b,c,l] > x[b,0,l] )
//
// R14: R12's decoupled producer/consumer pipe (best pipe body, ~33.8us) with
// finalization deferred to AFTER the row loop: per-(iteration,warp) partials
// go to a tiny smem array (896 B) via plain STS -- no waits, no barriers, no
// finalizer warp in the hot loop (R13's per-row free/done ring was the
// regression). One __syncthreads after the loop, then <=14 threads combine
// + logf + STG the CTA's outputs. Single launch.
// ---------------------------------------------------------------------------

#define MAX_L 2048
__device__ float g_slog[3 * MAX_L];            // fallback path scratch

#define FL 512
#define FC 21
#define FL2 (FL / 2)                            // 256 float2 per channel row
#define ROW_BYTES (FC * FL * 4)                 // 43008
#define GRIDP 304                               // 2 CTAs/SM
#define SMEM_DYN (2 * ROW_BYTES)                // 86016
#define NWC 8                                   // consumer warps
#define NTC (NWC * 32)                          // 256 consumer threads
#define NT (NTC + 32)                           // + producer warp
#define MAXIT 16                                // max rows per CTA (14 actual)

__device__ __forceinline__ uint32_t smem_u32(const void* p) {
    uint32_t a;
    asm("{ .reg .u64 t; cvta.to.shared.u64 t, %1; cvt.u32.u64 %0, t; }"
        : "=r"(a) : "l"(p));
    return a;
}
__device__ __forceinline__ void mbar_init(uint32_t mbar, uint32_t count) {
    asm volatile("mbarrier.init.shared.b64 [%0], %1;" :: "r"(mbar), "r"(count) : "memory");
}
__device__ __forceinline__ void mbar_arrive(uint32_t mbar) {
    asm volatile("mbarrier.arrive.shared.b64 _, [%0];" :: "r"(mbar) : "memory");
}
__device__ __forceinline__ void mbar_expect_tx(uint32_t mbar, uint32_t bytes) {
    asm volatile("mbarrier.arrive.expect_tx.shared.b64 _, [%0], %1;"
                 :: "r"(mbar), "r"(bytes) : "memory");
}
__device__ __forceinline__ void bulk_g2s(uint32_t dst, const void* src,
                                         uint32_t bytes, uint32_t mbar) {
    asm volatile(
        "cp.async.bulk.shared::cta.global.mbarrier::complete_tx::bytes "
        "[%0], [%1], %2, [%3];"
        :: "r"(dst), "l"(src), "r"(bytes), "r"(mbar) : "memory");
}
__device__ __forceinline__ void mbar_wait(uint32_t mbar, uint32_t parity) {
    uint32_t done;
    asm volatile(
        "{\n\t.reg .pred p;\n\t"
        "mbarrier.try_wait.parity.acquire.cta.shared::cta.b64 p, [%1], %2;\n\t"
        "selp.b32 %0, 1, 0, p;\n\t}"
        : "=r"(done) : "r"(mbar), "r"(parity) : "memory");
    if (!done) {
        asm volatile(
            "{\n\t.reg .pred P1;\n\t"
            "WAIT_LOOP_%=:\n\t"
            "mbarrier.try_wait.parity.acquire.cta.shared::cta.b64 P1, [%0], %1, 0x989680;\n\t"
            "@P1 bra.uni WAIT_DONE_%=;\n\t"
            "bra.uni WAIT_LOOP_%=;\n\t"
            "WAIT_DONE_%=:\n\t}"
            :: "r"(mbar), "r"(parity) : "memory");
    }
}

// ---- single-launch pipeline: producer + consumers, deferred finalize --------
__global__ void __launch_bounds__(NT, 2)
qpml_pipe(const float* __restrict__ x,
          const float* __restrict__ seq_hmm,
          const float* __restrict__ ss_hmm,
          const float* __restrict__ W,
          const float* __restrict__ bvec,
          float* __restrict__ out,
          int B, int H, int wstride)
{
    extern __shared__ __align__(16) float dyn[];
    const float2* buf2[2] = { (const float2*)dyn,
                              (const float2*)(dyn + FC * FL) };

    __shared__ float sW0[64], sW1[64], sW2[64];
    __shared__ __align__(8) unsigned long long mb_full[2], mb_empty[2];
    __shared__ float2 part[MAXIT][NWC];      // per-(iteration,warp) partials

    const int t = threadIdx.x;
    const int warp = t >> 5, lane = t & 31;
    const int cta = blockIdx.x;
    const int G = gridDim.x;

    if (t == 0) {
        mbar_init(smem_u32(&mb_full[0]), 1);
        mbar_init(smem_u32(&mb_full[1]), 1);
        mbar_init(smem_u32(&mb_empty[0]), NWC);
        mbar_init(smem_u32(&mb_empty[1]), NWC);
    }
    if (t < wstride && t < 64) {
        sW0[t] = __ldg(&W[0 * wstride + t]);
        sW1[t] = __ldg(&W[1 * wstride + t]);
        sW2[t] = __ldg(&W[2 * wstride + t]);
    }
    __syncthreads();

    const uint32_t bsm[2] = { smem_u32(buf2[0]), smem_u32(buf2[1]) };
    const uint32_t mf[2]  = { smem_u32(&mb_full[0]), smem_u32(&mb_full[1]) };
    const uint32_t me[2]  = { smem_u32(&mb_empty[0]), smem_u32(&mb_empty[1]) };

    if (warp == NWC) {
        // ---------------- producer warp ----------------
        if (lane == 0) {
            int phe[2] = {0, 0};
            int it = 0;
            for (long long r = cta; r < B; r += G, ++it) {
                const int k = it & 1;
                mbar_wait(me[k], phe[k]);      // pre-armed for it=0,1
                phe[k] ^= 1;
                mbar_expect_tx(mf[k], ROW_BYTES);
                bulk_g2s(bsm[k], (const char*)x + (size_t)r * ROW_BYTES,
                         ROW_BYTES, mf[k]);
            }
        }
        return;   // exited warp does not block later __syncthreads (sm_70+)
    }

    // ---------------- consumer warps ----------------
    // pre-arm both empty barriers (completes phase 0 of each)
    if (lane == 0) { mbar_arrive(me[0]); mbar_arrive(me[1]); }

    // per-thread tables for columns 2t, 2t+1 (overlaps first fills)
    float2 d10, d20, h0c, h1c, h2c;
    {
        float bb0 = __ldg(&bvec[0]), bb1 = __ldg(&bvec[1]), bb2 = __ldg(&bvec[2]);
        float2 s0 = make_float2(bb0, bb0);
        float2 s1 = make_float2(bb1, bb1);
        float2 s2 = make_float2(bb2, bb2);
        for (int h = 0; h < H; ++h) {
            float2 v = __ldg((const float2*)seq_hmm + h * FL2 + t);
            float w0 = sW0[20 + h], w1 = sW1[20 + h], w2 = sW2[20 + h];
            s0.x = fmaf(w0, v.x, s0.x); s0.y = fmaf(w0, v.y, s0.y);
            s1.x = fmaf(w1, v.x, s1.x); s1.y = fmaf(w1, v.y, s1.y);
            s2.x = fmaf(w2, v.x, s2.x); s2.y = fmaf(w2, v.y, s2.y);
        }
        d10 = make_float2(s1.x - s0.x, s1.y - s0.y);
        d20 = make_float2(s2.x - s0.x, s2.y - s0.y);
        h0c = __ldg((const float2*)ss_hmm + 0 * FL2 + t);
        h1c = __ldg((const float2*)ss_hmm + 1 * FL2 + t);
        h2c = __ldg((const float2*)ss_hmm + 2 * FL2 + t);
    }

    int phf[2] = {0, 0};
    int it = 0;
    for (long long r = cta; r < B; r += G, ++it) {
        const int k = it & 1;
        const float2* bk = buf2[k];

        mbar_wait(mf[k], phf[k]);
        phf[k] ^= 1;

        // ---- accumulation: ALL smem reads of buf[k] ----
        float2 v0 = bk[t];
        float mxx = -INFINITY, mxy = -INFINITY;
        float a0x = 0.f, a0y = 0.f;
        float a1x = 0.f, a1y = 0.f;
        float a2x = 0.f, a2y = 0.f;
        #pragma unroll
        for (int c = 1; c < FC; ++c) {
            float2 v = bk[c * FL2 + t];
            float w0 = sW0[c - 1], w1 = sW1[c - 1], w2 = sW2[c - 1];
            mxx = fmaxf(mxx, v.x);       mxy = fmaxf(mxy, v.y);
            a0x = fmaf(w0, v.x, a0x);    a0y = fmaf(w0, v.y, a0y);
            a1x = fmaf(w1, v.x, a1x);    a1y = fmaf(w1, v.y, a1y);
            a2x = fmaf(w2, v.x, a2x);    a2y = fmaf(w2, v.y, a2y);
        }

        // release buffer k immediately -- refill overlaps the tail below
        __syncwarp();
        if (lane == 0) mbar_arrive(me[k]);

        // ---- tail (no buf[k] reads): rebased softmax, e0 == 1 ----
        float e1x = __expf((a1x - a0x) + d10.x);
        float e2x = __expf((a2x - a0x) + d20.x);
        float e1y = __expf((a1y - a0y) + d10.y);
        float e2y = __expf((a2y - a0y) + d20.y);
        float numx = fmaf(h2c.x, e2x, fmaf(h1c.x, e1x, h0c.x));
        float denx = 1.f + e1x + e2x;
        float numy = fmaf(h2c.y, e2y, fmaf(h1c.y, e1y, h0c.y));
        float deny = 1.f + e1y + e2y;
        bool mxm = mxx > v0.x;
        bool mym = mxy > v0.y;
        float contrib = (mxm ? __fdividef(numx, denx) : 0.f)
                      + (mym ? __fdividef(numy, deny) : 0.f);
        float cnt = (mxm ? 1.f : 0.f) + (mym ? 1.f : 0.f);

        #pragma unroll
        for (int off = 16; off > 0; off >>= 1) {
            contrib += __shfl_down_sync(0xffffffffu, contrib, off);
            cnt     += __shfl_down_sync(0xffffffffu, cnt, off);
        }
        if (lane == 0)
            part[it][warp] = make_float2(contrib, cnt);   // plain STS, no sync
    }

    // ---- deferred finalize: one barrier, then <=MAXIT threads combine ----
    __syncthreads();
    if (t < it) {                       // it == rows this CTA processed
        const float2* p = part[t];
        float s = 0.f, c = 0.f;
        #pragma unroll
        for (int w = 0; w < NWC; ++w) {
            float2 v = p[w];
            s += v.x;
            c += v.y;
        }
        out[cta + (long long)t * G] = logf(s / c);
    }
}

// ---- fallback paths (non-512x21 shapes) --------------------------------------
__global__ void slog_kernel(const float* __restrict__ seq_hmm,
                            const float* __restrict__ W,
                            const float* __restrict__ bvec,
                            int L, int H, int wstride)
{
    int l = blockIdx.x * blockDim.x + threadIdx.x;
    if (l >= L) return;
    float s0 = bvec[0], s1 = bvec[1], s2 = bvec[2];
    for (int h = 0; h < H; ++h) {
        float v = __ldg(&seq_hmm[h * L + l]);
        s0 = fmaf(__ldg(&W[0 * wstride + 20 + h]), v, s0);
        s1 = fmaf(__ldg(&W[1 * wstride + 20 + h]), v, s1);
        s2 = fmaf(__ldg(&W[2 * wstride + 20 + h]), v, s2);
    }
    g_slog[0 * L + l] = s0;
    g_slog[1 * L + l] = s1;
    g_slog[2 * L + l] = s2;
}

__global__ void __launch_bounds__(128, 6)
qpml_generic(const float* __restrict__ x,
             const float* __restrict__ ss_hmm,
             const float* __restrict__ W,
             float* __restrict__ out,
             int L, int C, int wstride)
{
    const int b = blockIdx.x;
    const int t = threadIdx.x;
    const int Lv = L >> 2;

    __shared__ float sW0[20], sW1[20], sW2[20];
    if (t < 20) {
        sW0[t] = __ldg(&W[0 * wstride + t]);
        sW1[t] = __ldg(&W[1 * wstride + t]);
        sW2[t] = __ldg(&W[2 * wstride + t]);
    }
    __syncthreads();

    const float4* xb = (const float4*)(x + (size_t)b * (size_t)C * (size_t)L);
    float contrib = 0.f, cnt = 0.f;

    for (int i = t; i < Lv; i += 128) {
        float4 sl0 = __ldg((const float4*)&g_slog[0 * L] + i);
        float4 sl1 = __ldg((const float4*)&g_slog[1 * L] + i);
        float4 sl2 = __ldg((const float4*)&g_slog[2 * L] + i);
        float4 h0  = __ldg((const float4*)&ss_hmm[0 * L] + i);
        float4 h1  = __ldg((const float4*)&ss_hmm[1 * L] + i);
        float4 h2  = __ldg((const float4*)&ss_hmm[2 * L] + i);

        float4 v0 = __ldcs(&xb[i]);
        float x0[4] = {v0.x, v0.y, v0.z, v0.w};
        float mx[4] = {-INFINITY, -INFINITY, -INFINITY, -INFINITY};
        float a0[4] = {0.f, 0.f, 0.f, 0.f};
        float a1[4] = {0.f, 0.f, 0.f, 0.f};
        float a2[4] = {0.f, 0.f, 0.f, 0.f};

        for (int c = 1; c < C; ++c) {
            float4 v = __ldcs(&xb[c * Lv + i]);
            float vv[4] = {v.x, v.y, v.z, v.w};
            float w0 = sW0[c - 1], w1 = sW1[c - 1], w2 = sW2[c - 1];
            #pragma unroll
            for (int j = 0; j < 4; ++j) {
                mx[j] = fmaxf(mx[j], vv[j]);
                a0[j] = fmaf(w0, vv[j], a0[j]);
                a1[j] = fmaf(w1, vv[j], a1[j]);
                a2[j] = fmaf(w2, vv[j], a2[j]);
            }
        }

        float sla0[4] = {sl0.x, sl0.y, sl0.z, sl0.w};
        float sla1[4] = {sl1.x, sl1.y, sl1.z, sl1.w};
        float sla2[4] = {sl2.x, sl2.y, sl2.z, sl2.w};
        float ha0[4]  = {h0.x, h0.y, h0.z, h0.w};
        float ha1[4]  = {h1.x, h1.y, h1.z, h1.w};
        float ha2[4]  = {h2.x, h2.y, h2.z, h2.w};

        #pragma unroll
        for (int j = 0; j < 4; ++j) {
            float e0 = __expf(a0[j] + sla0[j]);
            float e1 = __expf(a1[j] + sla1[j]);
            float e2 = __expf(a2[j] + sla2[j]);
            float num = ha0[j] * e0 + ha1[j] * e1 + ha2[j] * e2;
            float den = e0 + e1 + e2;
            bool m = mx[j] > x0[j];
            contrib += m ? __fdividef(num, den) : 0.f;
            cnt     += m ? 1.f : 0.f;
        }
    }

    #pragma unroll
    for (int off = 16; off > 0; off >>= 1) {
        contrib += __shfl_down_sync(0xffffffffu, contrib, off);
        cnt     += __shfl_down_sync(0xffffffffu, cnt, off);
    }
    __shared__ float rs[2][4];
    if ((t & 31) == 0) { rs[0][t >> 5] = contrib; rs[1][t >> 5] = cnt; }
    __syncthreads();
    if (t == 0) {
        float s = rs[0][0] + rs[0][1] + rs[0][2] + rs[0][3];
        float c = rs[1][0] + rs[1][1] + rs[1][2] + rs[1][3];
        out[b] = logf(s / c);
    }
}

__global__ void qpml_kernel_scalar(const float* __restrict__ x,
                                   const float* __restrict__ ss_hmm,
                                   const float* __restrict__ W,
                                   float* __restrict__ out,
                                   int L, int C, int wstride)
{
    const int b = blockIdx.x;
    const int t = threadIdx.x;
    const float* xb = x + (size_t)b * (size_t)C * (size_t)L;

    float contrib = 0.f, cnt = 0.f;
    for (int l = t; l < L; l += blockDim.x) {
        float x0 = xb[l];
        float mx = -INFINITY;
        float a0 = 0.f, a1 = 0.f, a2 = 0.f;
        for (int c = 1; c < C; ++c) {
            float v = xb[c * L + l];
            mx = fmaxf(mx, v);
            a0 = fmaf(W[0 * wstride + c - 1], v, a0);
            a1 = fmaf(W[1 * wstride + c - 1], v, a1);
            a2 = fmaf(W[2 * wstride + c - 1], v, a2);
        }
        float e0 = __expf(a0 + g_slog[0 * L + l]);
        float e1 = __expf(a1 + g_slog[1 * L + l]);
        float e2 = __expf(a2 + g_slog[2 * L + l]);
        float num = ss_hmm[0 * L + l] * e0 + ss_hmm[1 * L + l] * e1
                  + ss_hmm[2 * L + l] * e2;
        if (mx > x0) { contrib += num / (e0 + e1 + e2); cnt += 1.f; }
    }
    #pragma unroll
    for (int off = 16; off > 0; off >>= 1) {
        contrib += __shfl_down_sync(0xffffffffu, contrib, off);
        cnt     += __shfl_down_sync(0xffffffffu, cnt, off);
    }
    __shared__ float rs[2][32];
    int nw = (blockDim.x + 31) >> 5;
    if ((t & 31) == 0) { rs[0][t >> 5] = contrib; rs[1][t >> 5] = cnt; }
    __syncthreads();
    if (t == 0) {
        float s = 0.f, c = 0.f;
        for (int w = 0; w < nw; ++w) { s += rs[0][w]; c += rs[1][w]; }
        out[b] = logf(s / c);
    }
}

extern "C" void kernel_launch(void* const* d_in, const int* in_sizes, int n_in,
                              void* d_out, int out_size)
{
    const float* x       = (const float*)d_in[0];   // [B, 21, L]
    const float* seq_hmm = (const float*)d_in[1];   // [H, L]
    const float* ss_hmm  = (const float*)d_in[2];   // [3, L]
    const float* W       = (const float*)d_in[3];   // [3, 20+H]
    const float* bvec    = (const float*)d_in[4];   // [3]
    float* out = (float*)d_out;

    const int B       = out_size;                   // 4096
    const int L       = in_sizes[2] / 3;            // 512
    const int H       = in_sizes[1] / L;            // 30
    const int C       = in_sizes[0] / (B * L);      // 21
    const int wstride = in_sizes[3] / 3;            // 20 + H = 50

    int grid = (B < GRIDP) ? B : GRIDP;
    int maxit = (B + grid - 1) / grid;

    if (C == FC && L == FL && H <= 44 && wstride <= 64 && maxit <= MAXIT) {
        cudaFuncSetAttribute(qpml_pipe,
                             cudaFuncAttributeMaxDynamicSharedMemorySize,
                             SMEM_DYN);
        qpml_pipe<<<grid, NT, SMEM_DYN>>>(x, seq_hmm, ss_hmm, W, bvec, out,
                                          B, H, wstride);
    } else if ((L & 3) == 0 && L <= MAX_L) {
        slog_kernel<<<(L + 255) / 256, 256>>>(seq_hmm, W, bvec, L, H, wstride);
        qpml_generic<<<B, 128>>>(x, ss_hmm, W, out, L, C, wstride);
    } else {
        slog_kernel<<<(L + 255) / 256, 256>>>(seq_hmm, W, bvec, L, H, wstride);
        qpml_kernel_scalar<<<B, 128>>>(x, ss_hmm, W, out, L, C, wstride);
    }
}